// round 8
// baseline (speedup 1.0000x reference)
#include <cuda_runtime.h>
#include <stdint.h>

// HashGridEncoder: instant-NGP multiresolution hash grid encode.
// x: [N,3] f32; aabb: [3] f32; table: [16, 2^19, 2] f32. out: [N,32] f32.
// Levels 0..2 dense (res 16/32/64), 3..15 hashed (v2 gathers — R7's v4
// pairing was mathematically wrong and is reverted).
// R8: level-0 table (17^3 = 4913 float2 = 39KB) cached in smem; its 8
// gathers/point move off the L1 wavefront budget onto the smem crossbar.

#define HG_TABLE_SIZE (1u << 19)
#define HG_MASK (HG_TABLE_SIZE - 1u)
#define HG_PRIME_Y 2654435761u
#define HG_PRIME_Z 805459861u
#define L0_ENTRIES 4913   // 17*17*17

struct LevelSetup {
    unsigned idx[8];
    float tx, ty, tz;
};

// l is compile-time constant in unrolled callers; dense/hashed branch folds.
__device__ __forceinline__ void level_setup(
    int l, float xn0, float xn1, float xn2, LevelSetup& s)
{
    const unsigned res = 16u << l;
    const float resf = (float)res;

    const float px = xn0 * resf, py = xn1 * resf, pz = xn2 * resf;
    const float fx = floorf(px), fy = floorf(py), fz = floorf(pz);
    s.tx = px - fx; s.ty = py - fy; s.tz = pz - fz;
    const unsigned cx = (unsigned)fx, cy = (unsigned)fy, cz = (unsigned)fz;

    if ((unsigned long long)(res + 1) * (res + 1) * (res + 1) <=
        (unsigned long long)HG_TABLE_SIZE) {
        const unsigned st = res + 1;
        const unsigned s2 = st * st;
        const unsigned base = cx + cy * st + cz * s2;
        s.idx[0] = base;           s.idx[1] = base + 1;
        s.idx[2] = base + st;      s.idx[3] = base + st + 1;
        s.idx[4] = base + s2;      s.idx[5] = base + s2 + 1;
        s.idx[6] = base + st + s2; s.idx[7] = base + st + s2 + 1;
    } else {
        const unsigned hy0 = cy * HG_PRIME_Y, hy1 = hy0 + HG_PRIME_Y;
        const unsigned hz0 = cz * HG_PRIME_Z, hz1 = hz0 + HG_PRIME_Z;
        const unsigned e00 = hy0 ^ hz0, e10 = hy1 ^ hz0;
        const unsigned e01 = hy0 ^ hz1, e11 = hy1 ^ hz1;
        const unsigned cx1 = cx + 1u;
        s.idx[0] = (cx  ^ e00) & HG_MASK;  s.idx[1] = (cx1 ^ e00) & HG_MASK;
        s.idx[2] = (cx  ^ e10) & HG_MASK;  s.idx[3] = (cx1 ^ e10) & HG_MASK;
        s.idx[4] = (cx  ^ e01) & HG_MASK;  s.idx[5] = (cx1 ^ e01) & HG_MASK;
        s.idx[6] = (cx  ^ e11) & HG_MASK;  s.idx[7] = (cx1 ^ e11) & HG_MASK;
    }
}

__device__ __forceinline__ void trilerp(
    const LevelSetup& s, const float vx[8], const float vy[8],
    float& f0, float& f1)
{
    const float wx1 = s.tx, wx0 = 1.0f - s.tx;
    const float wy1 = s.ty, wy0 = 1.0f - s.ty;
    const float wz1 = s.tz, wz0 = 1.0f - s.tz;
    const float w00 = wy0 * wz0, w10 = wy1 * wz0;
    const float w01 = wy0 * wz1, w11 = wy1 * wz1;
    const float w000 = wx0 * w00, w100 = wx1 * w00;
    const float w010 = wx0 * w10, w110 = wx1 * w10;
    const float w001 = wx0 * w01, w101 = wx1 * w01;
    const float w011 = wx0 * w11, w111 = wx1 * w11;

    f0 = w000 * vx[0] + w100 * vx[1] + w010 * vx[2] + w110 * vx[3] +
         w001 * vx[4] + w101 * vx[5] + w011 * vx[6] + w111 * vx[7];
    f1 = w000 * vy[0] + w100 * vy[1] + w010 * vy[2] + w110 * vy[3] +
         w001 * vy[4] + w101 * vy[5] + w011 * vy[6] + w111 * vy[7];
}

// Gather + trilerp CNT consecutive GLOBAL-memory levels starting at L0.
// Volatile asm loads: issued in program order before any consumer (proven
// necessary in R2/R4 — ptxas otherwise sinks the batch and kills MLP).
template <int L0, int CNT>
__device__ __forceinline__ void gather_levels(
    const float2* __restrict__ tab,
    float xn0, float xn1, float xn2,
    float* __restrict__ sline, int colbase)
{
    LevelSetup s[CNT];
#pragma unroll
    for (int i = 0; i < CNT; ++i)
        level_setup(L0 + i, xn0, xn1, xn2, s[i]);

    float vx[CNT][8], vy[CNT][8];
#pragma unroll
    for (int i = 0; i < CNT; ++i) {
        const float2* __restrict__ tl = tab + (size_t)(L0 + i) * HG_TABLE_SIZE;
#pragma unroll
        for (int j = 0; j < 8; ++j) {
            asm volatile("ld.global.nc.v2.f32 {%0, %1}, [%2];"
                         : "=f"(vx[i][j]), "=f"(vy[i][j])
                         : "l"(tl + s[i].idx[j]));
        }
    }

#pragma unroll
    for (int i = 0; i < CNT; ++i) {
        float f0, f1;
        trilerp(s[i], vx[i], vy[i], f0, f1);
        sline[colbase + 2 * i]     = f0;
        sline[colbase + 2 * i + 1] = f1;
    }
}

__global__ __launch_bounds__(256) void hashgrid_encode_kernel(
    const float* __restrict__ x,
    const float* __restrict__ aabb,
    const float* __restrict__ table,
    float* __restrict__ out,
    int n)
{
    // level-0 table cache (39.3KB) + per-warp half transpose tiles (17.4KB)
    __shared__ float2 l0tab[L0_ENTRIES];
    __shared__ float  sbuf[8][32][17];

    const int tid  = blockIdx.x * blockDim.x + threadIdx.x;
    const int warp = threadIdx.x >> 5;
    const int lane = threadIdx.x & 31;
    const bool active = (tid < n);
    const int pi = active ? tid : 0;   // clamp so gathers stay in-bounds

    const float2* __restrict__ tab = (const float2*)table;

    // cooperative load of level-0 table (coalesced, L2-resident source)
    for (int i = threadIdx.x; i < L0_ENTRIES; i += 256)
        l0tab[i] = tab[i];

    const float a0 = __ldg(aabb + 0);
    const float a1 = __ldg(aabb + 1);
    const float a2 = __ldg(aabb + 2);

    const float px_in = __ldg(x + 3 * (size_t)pi + 0);
    const float py_in = __ldg(x + 3 * (size_t)pi + 1);
    const float pz_in = __ldg(x + 3 * (size_t)pi + 2);

    // normalize_aabb then bound (-1,1) -> [0,1]; matches reference fp32 order
    const float xn0 = (px_in / a0 + 1.0f) * 0.5f;
    const float xn1 = (py_in / a1 + 1.0f) * 0.5f;
    const float xn2 = (pz_in / a2 + 1.0f) * 0.5f;

    float* sline = &sbuf[warp][lane][0];
    const int base_pt = blockIdx.x * blockDim.x + warp * 32;

    __syncthreads();   // l0tab ready

    // ---- half 0: levels 0..7 ----
    {
        // level 0 from smem; issue levels 1..3 global gathers first so they
        // are in flight while the smem path computes.
        LevelSetup s0;
        level_setup(0, xn0, xn1, xn2, s0);

        LevelSetup s[3];
        level_setup(1, xn0, xn1, xn2, s[0]);
        level_setup(2, xn0, xn1, xn2, s[1]);
        level_setup(3, xn0, xn1, xn2, s[2]);
        float vx[3][8], vy[3][8];
#pragma unroll
        for (int i = 0; i < 3; ++i) {
            const float2* __restrict__ tl =
                tab + (size_t)(1 + i) * HG_TABLE_SIZE;
#pragma unroll
            for (int j = 0; j < 8; ++j) {
                asm volatile("ld.global.nc.v2.f32 {%0, %1}, [%2];"
                             : "=f"(vx[i][j]), "=f"(vy[i][j])
                             : "l"(tl + s[i].idx[j]));
            }
        }

        // level 0 via smem crossbar
        float v0x[8], v0y[8];
#pragma unroll
        for (int j = 0; j < 8; ++j) {
            const float2 v = l0tab[s0.idx[j]];
            v0x[j] = v.x; v0y[j] = v.y;
        }
        float f0, f1;
        trilerp(s0, v0x, v0y, f0, f1);
        sline[0] = f0; sline[1] = f1;

#pragma unroll
        for (int i = 0; i < 3; ++i) {
            trilerp(s[i], vx[i], vy[i], f0, f1);
            sline[2 * (1 + i)]     = f0;
            sline[2 * (1 + i) + 1] = f1;
        }
    }
    gather_levels<4, 4>(tab, xn0, xn1, xn2, sline, 8);

    __syncwarp();
#pragma unroll
    for (int rr = 0; rr < 16; ++rr) {
        const int r = 2 * rr + (lane >> 4);
        const int c = lane & 15;
        const int pt = base_pt + r;
        if (pt < n) out[(size_t)pt * 32 + c] = sbuf[warp][r][c];
    }
    __syncwarp();

    // ---- half 1: levels 8..15 ----
    gather_levels<8, 4>(tab, xn0, xn1, xn2, sline, 0);
    gather_levels<12, 4>(tab, xn0, xn1, xn2, sline, 8);

    __syncwarp();
#pragma unroll
    for (int rr = 0; rr < 16; ++rr) {
        const int r = 2 * rr + (lane >> 4);
        const int c = lane & 15;
        const int pt = base_pt + r;
        if (pt < n) out[(size_t)pt * 32 + 16 + c] = sbuf[warp][r][c];
    }
}

extern "C" void kernel_launch(void* const* d_in, const int* in_sizes, int n_in,
                              void* d_out, int out_size) {
    const float* x     = (const float*)d_in[0];   // [N,3]
    const float* aabb  = (const float*)d_in[1];   // [3]
    const float* table = (const float*)d_in[2];   // [16, 2^19, 2]
    float* out = (float*)d_out;                   // [N, 32]

    const int n = in_sizes[0] / 3;
    const int threads = 256;
    const int blocks = (n + threads - 1) / threads;
    hashgrid_encode_kernel<<<blocks, threads>>>(x, aabb, table, out, n);
}

// round 9
// speedup vs baseline: 1.5089x; 1.5089x over previous
#include <cuda_runtime.h>
#include <stdint.h>

// HashGridEncoder: instant-NGP multiresolution hash grid encode.
// x: [N,3] f32; aabb: [3] f32; table: [16, 2^19, 2] f32. out: [N,32] f32.
// Levels 0..2 dense (res 16/32/64), 3..15 hashed.
// R9: for hashed levels, when cx is EVEN the two x-corners hash to the
// aligned index pair {q&~1, q|1} -> one v4 load replaces two v2 loads
// (halves lines touched). cx odd keeps the v2 path. Branch is per level;
// swap-selects are deferred to reduce time so load batching (MLP) survives.
// Skeleton = R5/R6 best (4-level volatile-asm batches, two half tiles).

#define HG_TABLE_SIZE (1u << 19)
#define HG_MASK (HG_TABLE_SIZE - 1u)
#define HG_PRIME_Y 2654435761u
#define HG_PRIME_Z 805459861u

// ---------------- dense levels (0..2) ----------------
struct DenseSetup {
    unsigned idx[8];
    float tx, ty, tz;
};

__device__ __forceinline__ void dense_setup(
    int l, float xn0, float xn1, float xn2, DenseSetup& s)
{
    const unsigned res = 16u << l;
    const float resf = (float)res;
    const float px = xn0 * resf, py = xn1 * resf, pz = xn2 * resf;
    const float fx = floorf(px), fy = floorf(py), fz = floorf(pz);
    s.tx = px - fx; s.ty = py - fy; s.tz = pz - fz;
    const unsigned cx = (unsigned)fx, cy = (unsigned)fy, cz = (unsigned)fz;
    const unsigned st = res + 1;
    const unsigned s2 = st * st;
    const unsigned base = cx + cy * st + cz * s2;
    s.idx[0] = base;           s.idx[1] = base + 1;
    s.idx[2] = base + st;      s.idx[3] = base + st + 1;
    s.idx[4] = base + s2;      s.idx[5] = base + s2 + 1;
    s.idx[6] = base + st + s2; s.idx[7] = base + st + s2 + 1;
}

__device__ __forceinline__ void dense_issue(
    const float2* __restrict__ tl, const DenseSetup& s,
    float vx[8], float vy[8])
{
#pragma unroll
    for (int j = 0; j < 8; ++j) {
        asm volatile("ld.global.nc.v2.f32 {%0, %1}, [%2];"
                     : "=f"(vx[j]), "=f"(vy[j])
                     : "l"(tl + s.idx[j]));
    }
}

// ---------------- hashed levels (3..15) ----------------
struct HashSetup {
    unsigned q[8];        // corner indices (x0,x1 per pair)
    float tx, ty, tz;
    unsigned even;        // 1 if cx is even -> pairs are {q&~1, q|1}
};

__device__ __forceinline__ void hash_setup(
    int l, float xn0, float xn1, float xn2, HashSetup& s)
{
    const unsigned res = 16u << l;
    const float resf = (float)res;
    const float px = xn0 * resf, py = xn1 * resf, pz = xn2 * resf;
    const float fx = floorf(px), fy = floorf(py), fz = floorf(pz);
    s.tx = px - fx; s.ty = py - fy; s.tz = pz - fz;
    const unsigned cx = (unsigned)fx, cy = (unsigned)fy, cz = (unsigned)fz;

    const unsigned hy0 = cy * HG_PRIME_Y, hy1 = hy0 + HG_PRIME_Y;
    const unsigned hz0 = cz * HG_PRIME_Z, hz1 = hz0 + HG_PRIME_Z;
    const unsigned e00 = hy0 ^ hz0, e10 = hy1 ^ hz0;
    const unsigned e01 = hy0 ^ hz1, e11 = hy1 ^ hz1;
    const unsigned cx1 = cx + 1u;
    s.q[0] = (cx  ^ e00) & HG_MASK;  s.q[1] = (cx1 ^ e00) & HG_MASK;
    s.q[2] = (cx  ^ e10) & HG_MASK;  s.q[3] = (cx1 ^ e10) & HG_MASK;
    s.q[4] = (cx  ^ e01) & HG_MASK;  s.q[5] = (cx1 ^ e01) & HG_MASK;
    s.q[6] = (cx  ^ e11) & HG_MASK;  s.q[7] = (cx1 ^ e11) & HG_MASK;
    s.even = (cx & 1u) ^ 1u;
}

// Issue this level's gathers. Even-cx lanes: 4x v4 (raw, unswapped into
// slots [2p]=(pair base entry), [2p+1]=(pair odd entry)). Odd-cx lanes:
// 8x v2 direct. Values are NOT consumed here (MLP preserved).
__device__ __forceinline__ void hash_issue(
    const float2* __restrict__ tl, const HashSetup& s,
    float vx[8], float vy[8])
{
    if (s.even) {
#pragma unroll
        for (int p = 0; p < 4; ++p) {
            const unsigned qa = s.q[2 * p] & ~1u;
            asm volatile("ld.global.nc.v4.f32 {%0, %1, %2, %3}, [%4];"
                         : "=f"(vx[2 * p]), "=f"(vy[2 * p]),
                           "=f"(vx[2 * p + 1]), "=f"(vy[2 * p + 1])
                         : "l"(tl + qa));
        }
    } else {
#pragma unroll
        for (int j = 0; j < 8; ++j) {
            asm volatile("ld.global.nc.v2.f32 {%0, %1}, [%2];"
                         : "=f"(vx[j]), "=f"(vy[j])
                         : "l"(tl + s.q[j]));
        }
    }
}

// Trilinear reduce with deferred swap fixup for the even-cx v4 path.
__device__ __forceinline__ void hash_reduce(
    const HashSetup& s, const float vx[8], const float vy[8],
    float& f0, float& f1)
{
    float x0f0[4], x0f1[4], x1f0[4], x1f1[4];
#pragma unroll
    for (int p = 0; p < 4; ++p) {
        // even path: slot [2p] holds entry qa (even index), [2p+1] holds qa|1.
        // corner x0 has index q[2p]; it is the odd entry iff q[2p]&1.
        const bool sw = s.even && (s.q[2 * p] & 1u);
        x0f0[p] = sw ? vx[2 * p + 1] : vx[2 * p];
        x0f1[p] = sw ? vy[2 * p + 1] : vy[2 * p];
        x1f0[p] = sw ? vx[2 * p]     : vx[2 * p + 1];
        x1f1[p] = sw ? vy[2 * p]     : vy[2 * p + 1];
    }

    const float wx1 = s.tx, wx0 = 1.0f - s.tx;
    const float wy1 = s.ty, wy0 = 1.0f - s.ty;
    const float wz1 = s.tz, wz0 = 1.0f - s.tz;
    const float w00 = wy0 * wz0, w10 = wy1 * wz0;
    const float w01 = wy0 * wz1, w11 = wy1 * wz1;
    const float w000 = wx0 * w00, w100 = wx1 * w00;
    const float w010 = wx0 * w10, w110 = wx1 * w10;
    const float w001 = wx0 * w01, w101 = wx1 * w01;
    const float w011 = wx0 * w11, w111 = wx1 * w11;

    f0 = w000 * x0f0[0] + w100 * x1f0[0] + w010 * x0f0[1] + w110 * x1f0[1] +
         w001 * x0f0[2] + w101 * x1f0[2] + w011 * x0f0[3] + w111 * x1f0[3];
    f1 = w000 * x0f1[0] + w100 * x1f1[0] + w010 * x0f1[1] + w110 * x1f1[1] +
         w001 * x0f1[2] + w101 * x1f1[2] + w011 * x0f1[3] + w111 * x1f1[3];
}

__device__ __forceinline__ void dense_reduce(
    const DenseSetup& s, const float vx[8], const float vy[8],
    float& f0, float& f1)
{
    const float wx1 = s.tx, wx0 = 1.0f - s.tx;
    const float wy1 = s.ty, wy0 = 1.0f - s.ty;
    const float wz1 = s.tz, wz0 = 1.0f - s.tz;
    const float w00 = wy0 * wz0, w10 = wy1 * wz0;
    const float w01 = wy0 * wz1, w11 = wy1 * wz1;
    const float w000 = wx0 * w00, w100 = wx1 * w00;
    const float w010 = wx0 * w10, w110 = wx1 * w10;
    const float w001 = wx0 * w01, w101 = wx1 * w01;
    const float w011 = wx0 * w11, w111 = wx1 * w11;

    f0 = w000 * vx[0] + w100 * vx[1] + w010 * vx[2] + w110 * vx[3] +
         w001 * vx[4] + w101 * vx[5] + w011 * vx[6] + w111 * vx[7];
    f1 = w000 * vy[0] + w100 * vy[1] + w010 * vy[2] + w110 * vy[3] +
         w001 * vy[4] + w101 * vy[5] + w011 * vy[6] + w111 * vy[7];
}

// ---- batch of 4 hashed levels L0..L0+3: all issues, then all reduces ----
template <int L0>
__device__ __forceinline__ void batch_hashed4(
    const float2* __restrict__ tab,
    float xn0, float xn1, float xn2,
    float* __restrict__ sline, int colbase)
{
    HashSetup s[4];
#pragma unroll
    for (int i = 0; i < 4; ++i)
        hash_setup(L0 + i, xn0, xn1, xn2, s[i]);

    float vx[4][8], vy[4][8];
#pragma unroll
    for (int i = 0; i < 4; ++i)
        hash_issue(tab + (size_t)(L0 + i) * HG_TABLE_SIZE, s[i], vx[i], vy[i]);

#pragma unroll
    for (int i = 0; i < 4; ++i) {
        float f0, f1;
        hash_reduce(s[i], vx[i], vy[i], f0, f1);
        sline[colbase + 2 * i]     = f0;
        sline[colbase + 2 * i + 1] = f1;
    }
}

// ---- batch 0: dense 0..2 + hashed 3 ----
__device__ __forceinline__ void batch_mixed(
    const float2* __restrict__ tab,
    float xn0, float xn1, float xn2, float* __restrict__ sline)
{
    DenseSetup d[3];
    HashSetup  h;
    dense_setup(0, xn0, xn1, xn2, d[0]);
    dense_setup(1, xn0, xn1, xn2, d[1]);
    dense_setup(2, xn0, xn1, xn2, d[2]);
    hash_setup(3, xn0, xn1, xn2, h);

    float vx[4][8], vy[4][8];
    dense_issue(tab + 0 * (size_t)HG_TABLE_SIZE, d[0], vx[0], vy[0]);
    dense_issue(tab + 1 * (size_t)HG_TABLE_SIZE, d[1], vx[1], vy[1]);
    dense_issue(tab + 2 * (size_t)HG_TABLE_SIZE, d[2], vx[2], vy[2]);
    hash_issue (tab + 3 * (size_t)HG_TABLE_SIZE, h,    vx[3], vy[3]);

    float f0, f1;
#pragma unroll
    for (int i = 0; i < 3; ++i) {
        dense_reduce(d[i], vx[i], vy[i], f0, f1);
        sline[2 * i]     = f0;
        sline[2 * i + 1] = f1;
    }
    hash_reduce(h, vx[3], vy[3], f0, f1);
    sline[6] = f0; sline[7] = f1;
}

__global__ __launch_bounds__(128) void hashgrid_encode_kernel(
    const float* __restrict__ x,
    const float* __restrict__ aabb,
    const float* __restrict__ table,
    float* __restrict__ out,
    int n)
{
    // per-warp HALF tile: 32 points x 16 feats (levels 0-7, reused for 8-15)
    __shared__ float sbuf[4][32][17];

    const int tid  = blockIdx.x * blockDim.x + threadIdx.x;
    const int warp = threadIdx.x >> 5;
    const int lane = threadIdx.x & 31;
    const bool active = (tid < n);
    const int pi = active ? tid : 0;   // clamp so gathers stay in-bounds

    const float a0 = __ldg(aabb + 0);
    const float a1 = __ldg(aabb + 1);
    const float a2 = __ldg(aabb + 2);

    const float px_in = __ldg(x + 3 * (size_t)pi + 0);
    const float py_in = __ldg(x + 3 * (size_t)pi + 1);
    const float pz_in = __ldg(x + 3 * (size_t)pi + 2);

    // normalize_aabb then bound (-1,1) -> [0,1]; matches reference fp32 order
    const float xn0 = (px_in / a0 + 1.0f) * 0.5f;
    const float xn1 = (py_in / a1 + 1.0f) * 0.5f;
    const float xn2 = (pz_in / a2 + 1.0f) * 0.5f;

    const float2* __restrict__ tab = (const float2*)table;
    float* sline = &sbuf[warp][lane][0];
    const int base_pt = blockIdx.x * blockDim.x + warp * 32;

    // ---- half 0: levels 0..7 ----
    batch_mixed(tab, xn0, xn1, xn2, sline);
    batch_hashed4<4>(tab, xn0, xn1, xn2, sline, 8);
    __syncwarp();
#pragma unroll
    for (int rr = 0; rr < 16; ++rr) {
        const int r = 2 * rr + (lane >> 4);
        const int c = lane & 15;
        const int pt = base_pt + r;
        if (pt < n) out[(size_t)pt * 32 + c] = sbuf[warp][r][c];
    }
    __syncwarp();

    // ---- half 1: levels 8..15 ----
    batch_hashed4<8>(tab, xn0, xn1, xn2, sline, 0);
    batch_hashed4<12>(tab, xn0, xn1, xn2, sline, 8);
    __syncwarp();
#pragma unroll
    for (int rr = 0; rr < 16; ++rr) {
        const int r = 2 * rr + (lane >> 4);
        const int c = lane & 15;
        const int pt = base_pt + r;
        if (pt < n) out[(size_t)pt * 32 + 16 + c] = sbuf[warp][r][c];
    }
}

extern "C" void kernel_launch(void* const* d_in, const int* in_sizes, int n_in,
                              void* d_out, int out_size) {
    const float* x     = (const float*)d_in[0];   // [N,3]
    const float* aabb  = (const float*)d_in[1];   // [3]
    const float* table = (const float*)d_in[2];   // [16, 2^19, 2]
    float* out = (float*)d_out;                   // [N, 32]

    const int n = in_sizes[0] / 3;
    const int threads = 128;
    const int blocks = (n + threads - 1) / threads;
    hashgrid_encode_kernel<<<blocks, threads>>>(x, aabb, table, out, n);
}

// round 10
// speedup vs baseline: 1.5392x; 1.0201x over previous
#include <cuda_runtime.h>
#include <stdint.h>

// HashGridEncoder: instant-NGP multiresolution hash grid encode.
// x: [N,3] f32; aabb: [3] f32; table: [16, 2^19, 2] f32. out: [N,32] f32.
// Levels 0..2 dense (res 16/32/64), 3..15 hashed.
// R10: (a) dense levels get BRANCHLESS v4 pairing: pair parities are
// {p,~p,~p,p} (st, st^2 odd), so exactly 2 pairs are even-aligned per lane;
// select their addresses, 2xv4 + 4xv2 instead of 8xv2. (b) hashed batches
// 4->3 levels to cut live regs (156 -> ~110) and raise occupancy.

#define HG_TABLE_SIZE (1u << 19)
#define HG_MASK (HG_TABLE_SIZE - 1u)
#define HG_PRIME_Y 2654435761u
#define HG_PRIME_Z 805459861u

// ---------------- dense levels (0..2): branchless paired loads -------------
struct DenseSetup {
    unsigned addrA, addrB;   // even-aligned pair base indices (v4 targets)
    unsigned oX, oY;         // odd pairs' first corner indices (v2 targets)
    unsigned e;              // 1 if base is even
    float tx, ty, tz;
};

__device__ __forceinline__ void dense_setup(
    int l, float xn0, float xn1, float xn2, DenseSetup& s)
{
    const unsigned res = 16u << l;
    const float resf = (float)res;
    const float px = xn0 * resf, py = xn1 * resf, pz = xn2 * resf;
    const float fx = floorf(px), fy = floorf(py), fz = floorf(pz);
    s.tx = px - fx; s.ty = py - fy; s.tz = pz - fz;
    const unsigned cx = (unsigned)fx, cy = (unsigned)fy, cz = (unsigned)fz;
    const unsigned st = res + 1;          // odd
    const unsigned s2 = st * st;          // odd
    const unsigned base = cx + cy * st + cz * s2;
    const unsigned e = (base & 1u) ^ 1u;  // 1 if base even
    s.e = e;
    // pairs: P0=base(p) P1=base+st(~p) P2=base+s2(~p) P3=base+st+s2(p)
    s.addrA = e ? base           : base + st;   // even pair (P0 or P1)
    s.addrB = e ? base + st + s2 : base + s2;   // even pair (P3 or P2)
    s.oX    = e ? base + st      : base;        // odd pair  (P1 or P0)
    s.oY    = e ? base + s2      : base + st + s2; // odd pair (P2 or P3)
}

struct DenseVals {
    float ax0, ay0, ax1, ay1;   // v4 A: slot0 (f0,f1), slot1 (f0,f1)
    float bx0, by0, bx1, by1;   // v4 B
    float Xx0, Xy0, Xx1, Xy1;   // v2 pair X (oX, oX+1)
    float Yx0, Yy0, Yx1, Yy1;   // v2 pair Y (oY, oY+1)
};

__device__ __forceinline__ void dense_issue(
    const float2* __restrict__ tl, const DenseSetup& s, DenseVals& v)
{
    asm volatile("ld.global.nc.v4.f32 {%0, %1, %2, %3}, [%4];"
                 : "=f"(v.ax0), "=f"(v.ay0), "=f"(v.ax1), "=f"(v.ay1)
                 : "l"(tl + s.addrA));
    asm volatile("ld.global.nc.v4.f32 {%0, %1, %2, %3}, [%4];"
                 : "=f"(v.bx0), "=f"(v.by0), "=f"(v.bx1), "=f"(v.by1)
                 : "l"(tl + s.addrB));
    asm volatile("ld.global.nc.v2.f32 {%0, %1}, [%2];"
                 : "=f"(v.Xx0), "=f"(v.Xy0) : "l"(tl + s.oX));
    asm volatile("ld.global.nc.v2.f32 {%0, %1}, [%2];"
                 : "=f"(v.Xx1), "=f"(v.Xy1) : "l"(tl + s.oX + 1));
    asm volatile("ld.global.nc.v2.f32 {%0, %1}, [%2];"
                 : "=f"(v.Yx0), "=f"(v.Yy0) : "l"(tl + s.oY));
    asm volatile("ld.global.nc.v2.f32 {%0, %1}, [%2];"
                 : "=f"(v.Yx1), "=f"(v.Yy1) : "l"(tl + s.oY + 1));
}

__device__ __forceinline__ void dense_reduce(
    const DenseSetup& s, const DenseVals& v, float& f0, float& f1)
{
    const bool e = s.e != 0;
    // corner values (f0,f1) per pair, unscrambled:
    // P0 (000,100): e ? A : X ; P1 (010,110): e ? X : A
    // P2 (001,101): e ? Y : B ; P3 (011,111): e ? B : Y
    const float c000x = e ? v.ax0 : v.Xx0, c000y = e ? v.ay0 : v.Xy0;
    const float c100x = e ? v.ax1 : v.Xx1, c100y = e ? v.ay1 : v.Xy1;
    const float c010x = e ? v.Xx0 : v.ax0, c010y = e ? v.Xy0 : v.ay0;
    const float c110x = e ? v.Xx1 : v.ax1, c110y = e ? v.Xy1 : v.ay1;
    const float c001x = e ? v.Yx0 : v.bx0, c001y = e ? v.Yy0 : v.by0;
    const float c101x = e ? v.Yx1 : v.bx1, c101y = e ? v.Yy1 : v.by1;
    const float c011x = e ? v.bx0 : v.Yx0, c011y = e ? v.by0 : v.Yy0;
    const float c111x = e ? v.bx1 : v.Yx1, c111y = e ? v.by1 : v.Yy1;

    const float wx1 = s.tx, wx0 = 1.0f - s.tx;
    const float wy1 = s.ty, wy0 = 1.0f - s.ty;
    const float wz1 = s.tz, wz0 = 1.0f - s.tz;
    const float w00 = wy0 * wz0, w10 = wy1 * wz0;
    const float w01 = wy0 * wz1, w11 = wy1 * wz1;
    const float w000 = wx0 * w00, w100 = wx1 * w00;
    const float w010 = wx0 * w10, w110 = wx1 * w10;
    const float w001 = wx0 * w01, w101 = wx1 * w01;
    const float w011 = wx0 * w11, w111 = wx1 * w11;

    f0 = w000 * c000x + w100 * c100x + w010 * c010x + w110 * c110x +
         w001 * c001x + w101 * c101x + w011 * c011x + w111 * c111x;
    f1 = w000 * c000y + w100 * c100y + w010 * c010y + w110 * c110y +
         w001 * c001y + w101 * c101y + w011 * c011y + w111 * c111y;
}

// ---------------- hashed levels (3..15): R9 proven path --------------------
struct HashSetup {
    unsigned q[8];
    float tx, ty, tz;
    unsigned even;        // 1 if cx even -> x-pairs are aligned {q&~1, q|1}
};

__device__ __forceinline__ void hash_setup(
    int l, float xn0, float xn1, float xn2, HashSetup& s)
{
    const unsigned res = 16u << l;
    const float resf = (float)res;
    const float px = xn0 * resf, py = xn1 * resf, pz = xn2 * resf;
    const float fx = floorf(px), fy = floorf(py), fz = floorf(pz);
    s.tx = px - fx; s.ty = py - fy; s.tz = pz - fz;
    const unsigned cx = (unsigned)fx, cy = (unsigned)fy, cz = (unsigned)fz;

    const unsigned hy0 = cy * HG_PRIME_Y, hy1 = hy0 + HG_PRIME_Y;
    const unsigned hz0 = cz * HG_PRIME_Z, hz1 = hz0 + HG_PRIME_Z;
    const unsigned e00 = hy0 ^ hz0, e10 = hy1 ^ hz0;
    const unsigned e01 = hy0 ^ hz1, e11 = hy1 ^ hz1;
    const unsigned cx1 = cx + 1u;
    s.q[0] = (cx  ^ e00) & HG_MASK;  s.q[1] = (cx1 ^ e00) & HG_MASK;
    s.q[2] = (cx  ^ e10) & HG_MASK;  s.q[3] = (cx1 ^ e10) & HG_MASK;
    s.q[4] = (cx  ^ e01) & HG_MASK;  s.q[5] = (cx1 ^ e01) & HG_MASK;
    s.q[6] = (cx  ^ e11) & HG_MASK;  s.q[7] = (cx1 ^ e11) & HG_MASK;
    s.even = (cx & 1u) ^ 1u;
}

__device__ __forceinline__ void hash_issue(
    const float2* __restrict__ tl, const HashSetup& s,
    float vx[8], float vy[8])
{
    if (s.even) {
#pragma unroll
        for (int p = 0; p < 4; ++p) {
            const unsigned qa = s.q[2 * p] & ~1u;
            asm volatile("ld.global.nc.v4.f32 {%0, %1, %2, %3}, [%4];"
                         : "=f"(vx[2 * p]), "=f"(vy[2 * p]),
                           "=f"(vx[2 * p + 1]), "=f"(vy[2 * p + 1])
                         : "l"(tl + qa));
        }
    } else {
#pragma unroll
        for (int j = 0; j < 8; ++j) {
            asm volatile("ld.global.nc.v2.f32 {%0, %1}, [%2];"
                         : "=f"(vx[j]), "=f"(vy[j])
                         : "l"(tl + s.q[j]));
        }
    }
}

__device__ __forceinline__ void hash_reduce(
    const HashSetup& s, const float vx[8], const float vy[8],
    float& f0, float& f1)
{
    float x0f0[4], x0f1[4], x1f0[4], x1f1[4];
#pragma unroll
    for (int p = 0; p < 4; ++p) {
        const bool sw = s.even && (s.q[2 * p] & 1u);
        x0f0[p] = sw ? vx[2 * p + 1] : vx[2 * p];
        x0f1[p] = sw ? vy[2 * p + 1] : vy[2 * p];
        x1f0[p] = sw ? vx[2 * p]     : vx[2 * p + 1];
        x1f1[p] = sw ? vy[2 * p]     : vy[2 * p + 1];
    }

    const float wx1 = s.tx, wx0 = 1.0f - s.tx;
    const float wy1 = s.ty, wy0 = 1.0f - s.ty;
    const float wz1 = s.tz, wz0 = 1.0f - s.tz;
    const float w00 = wy0 * wz0, w10 = wy1 * wz0;
    const float w01 = wy0 * wz1, w11 = wy1 * wz1;
    const float w000 = wx0 * w00, w100 = wx1 * w00;
    const float w010 = wx0 * w10, w110 = wx1 * w10;
    const float w001 = wx0 * w01, w101 = wx1 * w01;
    const float w011 = wx0 * w11, w111 = wx1 * w11;

    f0 = w000 * x0f0[0] + w100 * x1f0[0] + w010 * x0f0[1] + w110 * x1f0[1] +
         w001 * x0f0[2] + w101 * x1f0[2] + w011 * x0f0[3] + w111 * x1f0[3];
    f1 = w000 * x0f1[0] + w100 * x1f1[0] + w010 * x0f1[1] + w110 * x1f1[1] +
         w001 * x0f1[2] + w101 * x1f1[2] + w011 * x0f1[3] + w111 * x1f1[3];
}

// ---- batch: dense levels 0..2 (cols 0..5) ----
__device__ __forceinline__ void batch_dense3(
    const float2* __restrict__ tab,
    float xn0, float xn1, float xn2, float* __restrict__ sline)
{
    DenseSetup s[3];
    dense_setup(0, xn0, xn1, xn2, s[0]);
    dense_setup(1, xn0, xn1, xn2, s[1]);
    dense_setup(2, xn0, xn1, xn2, s[2]);

    DenseVals v[3];
#pragma unroll
    for (int i = 0; i < 3; ++i)
        dense_issue(tab + (size_t)i * HG_TABLE_SIZE, s[i], v[i]);

#pragma unroll
    for (int i = 0; i < 3; ++i) {
        float f0, f1;
        dense_reduce(s[i], v[i], f0, f1);
        sline[2 * i]     = f0;
        sline[2 * i + 1] = f1;
    }
}

// ---- batch: CNT hashed levels L0.. (cols colbase..) ----
template <int L0, int CNT>
__device__ __forceinline__ void batch_hashed(
    const float2* __restrict__ tab,
    float xn0, float xn1, float xn2,
    float* __restrict__ sline, int colbase)
{
    HashSetup s[CNT];
#pragma unroll
    for (int i = 0; i < CNT; ++i)
        hash_setup(L0 + i, xn0, xn1, xn2, s[i]);

    float vx[CNT][8], vy[CNT][8];
#pragma unroll
    for (int i = 0; i < CNT; ++i)
        hash_issue(tab + (size_t)(L0 + i) * HG_TABLE_SIZE, s[i], vx[i], vy[i]);

#pragma unroll
    for (int i = 0; i < CNT; ++i) {
        float f0, f1;
        hash_reduce(s[i], vx[i], vy[i], f0, f1);
        sline[colbase + 2 * i]     = f0;
        sline[colbase + 2 * i + 1] = f1;
    }
}

__global__ __launch_bounds__(128) void hashgrid_encode_kernel(
    const float* __restrict__ x,
    const float* __restrict__ aabb,
    const float* __restrict__ table,
    float* __restrict__ out,
    int n)
{
    // per-warp HALF tile: 32 points x 16 feats (levels 0-7, reused for 8-15)
    __shared__ float sbuf[4][32][17];

    const int tid  = blockIdx.x * blockDim.x + threadIdx.x;
    const int warp = threadIdx.x >> 5;
    const int lane = threadIdx.x & 31;
    const bool active = (tid < n);
    const int pi = active ? tid : 0;   // clamp so gathers stay in-bounds

    const float a0 = __ldg(aabb + 0);
    const float a1 = __ldg(aabb + 1);
    const float a2 = __ldg(aabb + 2);

    const float px_in = __ldg(x + 3 * (size_t)pi + 0);
    const float py_in = __ldg(x + 3 * (size_t)pi + 1);
    const float pz_in = __ldg(x + 3 * (size_t)pi + 2);

    // normalize_aabb then bound (-1,1) -> [0,1]; matches reference fp32 order
    const float xn0 = (px_in / a0 + 1.0f) * 0.5f;
    const float xn1 = (py_in / a1 + 1.0f) * 0.5f;
    const float xn2 = (pz_in / a2 + 1.0f) * 0.5f;

    const float2* __restrict__ tab = (const float2*)table;
    float* sline = &sbuf[warp][lane][0];
    const int base_pt = blockIdx.x * blockDim.x + warp * 32;

    // ---- half 0: levels 0..7 ----
    batch_dense3(tab, xn0, xn1, xn2, sline);               // cols 0..5
    batch_hashed<3, 3>(tab, xn0, xn1, xn2, sline, 6);      // cols 6..11
    batch_hashed<6, 2>(tab, xn0, xn1, xn2, sline, 12);     // cols 12..15
    __syncwarp();
#pragma unroll
    for (int rr = 0; rr < 16; ++rr) {
        const int r = 2 * rr + (lane >> 4);
        const int c = lane & 15;
        const int pt = base_pt + r;
        if (pt < n) out[(size_t)pt * 32 + c] = sbuf[warp][r][c];
    }
    __syncwarp();

    // ---- half 1: levels 8..15 ----
    batch_hashed<8, 3>(tab, xn0, xn1, xn2, sline, 0);      // cols 0..5
    batch_hashed<11, 3>(tab, xn0, xn1, xn2, sline, 6);     // cols 6..11
    batch_hashed<14, 2>(tab, xn0, xn1, xn2, sline, 12);    // cols 12..15
    __syncwarp();
#pragma unroll
    for (int rr = 0; rr < 16; ++rr) {
        const int r = 2 * rr + (lane >> 4);
        const int c = lane & 15;
        const int pt = base_pt + r;
        if (pt < n) out[(size_t)pt * 32 + 16 + c] = sbuf[warp][r][c];
    }
}

extern "C" void kernel_launch(void* const* d_in, const int* in_sizes, int n_in,
                              void* d_out, int out_size) {
    const float* x     = (const float*)d_in[0];   // [N,3]
    const float* aabb  = (const float*)d_in[1];   // [3]
    const float* table = (const float*)d_in[2];   // [16, 2^19, 2]
    float* out = (float*)d_out;                   // [N, 32]

    const int n = in_sizes[0] / 3;
    const int threads = 128;
    const int blocks = (n + threads - 1) / threads;
    hashgrid_encode_kernel<<<blocks, threads>>>(x, aabb, table, out, n);
}